// round 14
// baseline (speedup 1.0000x reference)
#include <cuda_runtime.h>
#include <cuda_fp16.h>
#include <math.h>

// Problem constants (static in the reference)
#define EMBED   256
#define HEADS   8
#define LEVELS  3
#define POINTS  4
#define DHEAD   32
#define BATCH   2
#define SEQ     21504          // 128*128 + 64*64 + 32*32
#define NQUERY  21504
#define MROWS   (BATCH * NQUERY)   // 43008

#define SEQP    (SEQ + 2)                 // padded pixels per (b,h) plane
#define NPLANE  (BATCH * HEADS)           // 16
#define CPYB_H  ((size_t)NPLANE * SEQP * DHEAD)   // halves per copy
#define CPYB_U4 (CPYB_H / 8)                      // uint4 per copy

// Scratch (device globals; no allocation allowed)
__device__ uint4  g_valrep[2 * CPYB_U4];          // fp16 value [copy][B,H,Sp,D]
__device__ __half g_hidden_h[(size_t)MROWS * EMBED];
__device__ __half g_enc_h   [(size_t)BATCH * SEQ * EMBED];
__device__ __half g_valw_h  [256 * 256];
__device__ __half g_outw_h  [256 * 256];
__device__ __half g_obw_h   [288 * 256];          // off(192) + aw(96) weights
__device__ float  g_obb     [288];                // concat bias
__device__ __half g_offaw_h [(size_t)MROWS * 288];// fused off+aw output (fp16)

// ---------------------------------------------------------------------------
// Mega fp32->fp16 conversion: hidden, enc, val_w, out_w, off_w|aw_w concat.
// ---------------------------------------------------------------------------
#define SEG_H   1376256                 // hidden uint4
#define SEG_E   (SEG_H + 1376256)       // enc
#define SEG_VW  (SEG_E + 8192)
#define SEG_OW  (SEG_VW + 8192)
#define SEG_OFW (SEG_OW + 6144)
#define SEG_AWW (SEG_OFW + 3072)        // total 2778112

__global__ void f2h_mega(const float4* __restrict__ hidden,
                         const float4* __restrict__ enc,
                         const float4* __restrict__ valw,
                         const float4* __restrict__ outw,
                         const float4* __restrict__ offw,
                         const float4* __restrict__ aww,
                         const float*  __restrict__ offb,
                         const float*  __restrict__ awb)
{
    const int gid = blockIdx.x * blockDim.x + threadIdx.x;
    if (gid < 288)
        g_obb[gid] = (gid < 192) ? offb[gid] : awb[gid - 192];
    if (gid >= SEG_AWW) return;

    const float4* src;
    uint4* dst;
    int idx;
    if (gid < SEG_H)        { src = hidden; dst = (uint4*)g_hidden_h; idx = gid; }
    else if (gid < SEG_E)   { src = enc;    dst = (uint4*)g_enc_h;    idx = gid - SEG_H; }
    else if (gid < SEG_VW)  { src = valw;   dst = (uint4*)g_valw_h;   idx = gid - SEG_E; }
    else if (gid < SEG_OW)  { src = outw;   dst = (uint4*)g_outw_h;   idx = gid - SEG_VW; }
    else if (gid < SEG_OFW) { src = offw;   dst = (uint4*)g_obw_h;    idx = gid - SEG_OW; }
    else                    { src = aww;    dst = (uint4*)g_obw_h + 6144; idx = gid - SEG_OFW; }

    float4 f0 = src[2 * idx];
    float4 f1 = src[2 * idx + 1];
    __half2 h0 = __floats2half2_rn(f0.x, f0.y);
    __half2 h1 = __floats2half2_rn(f0.z, f0.w);
    __half2 h2 = __floats2half2_rn(f1.x, f1.y);
    __half2 h3 = __floats2half2_rn(f1.z, f1.w);
    uint4 o;
    o.x = *reinterpret_cast<unsigned*>(&h0);
    o.y = *reinterpret_cast<unsigned*>(&h1);
    o.z = *reinterpret_cast<unsigned*>(&h2);
    o.w = *reinterpret_cast<unsigned*>(&h3);
    dst[idx] = o;
}

__device__ __forceinline__ void cp_async16(unsigned smem_addr, const void* gptr, int src_size) {
    asm volatile("cp.async.cg.shared.global [%0], [%1], 16, %2;\n"
                 :: "r"(smem_addr), "l"(gptr), "r"(src_size));
}
__device__ __forceinline__ void ldmatrix_x4(unsigned* r, unsigned addr) {
    asm volatile("ldmatrix.sync.aligned.m8n8.x4.shared.b16 {%0,%1,%2,%3}, [%4];"
                 : "=r"(r[0]), "=r"(r[1]), "=r"(r[2]), "=r"(r[3]) : "r"(addr));
}

extern __shared__ char smem_dyn[];

// ---------------------------------------------------------------------------
// R11-proven FP16 GEMM core for the two projection GEMMs.
// BM=128, BN=128, BK=32, 4-stage cp.async (16KB/stage, 64KB dynamic smem).
// MODE: 1 = value replicated fp16 (g_valrep), 2 = fp16 row-288 (g_offaw_h)
// ---------------------------------------------------------------------------
template<int MODE>
__device__ __forceinline__ void hgemm_core(
    const __half* __restrict__ A, const __half* __restrict__ W,
    const float* __restrict__ bias, int N, int n0)
{
    const int K = 256;
    const unsigned smem_u = (unsigned)__cvta_generic_to_shared(smem_dyn);

    const int tid  = threadIdx.x;
    const int wid  = tid >> 5;
    const int lane = tid & 31;

    const int m0 = blockIdx.y * 128;
    const int warp_m = (wid & 3) * 32;
    const int warp_n = (wid >> 2) * 64;

    float acc[2][8][4];
#pragma unroll
    for (int mi = 0; mi < 2; mi++)
#pragma unroll
        for (int ni = 0; ni < 8; ni++)
#pragma unroll
            for (int c = 0; c < 4; c++) acc[mi][ni][c] = 0.f;

    auto load_stage = [&](int stage, int k0) {
        const unsigned a_base = smem_u + stage * 16384;
        const unsigned w_base = a_base + 8192;
#pragma unroll
        for (int i = 0; i < 2; i++) {
            int idx = tid + i * 256;
            int r = idx >> 2, c = idx & 3;
            int pr = r >> 1;
            int slot = (c | ((r & 1) << 2)) ^ (pr & 7);
            cp_async16(a_base + pr * 128 + slot * 16,
                       &A[(size_t)(m0 + r) * K + k0 + c * 8], 16);
        }
#pragma unroll
        for (int i = 0; i < 2; i++) {
            int idx = tid + i * 256;
            int r = idx >> 2, c = idx & 3;
            int pr = r >> 1;
            int slot = (c | ((r & 1) << 2)) ^ (pr & 7);
            int n  = n0 + r;
            int ok = (n < N) ? 16 : 0;
            const __half* src = (n < N) ? &W[(size_t)n * K + k0 + c * 8] : W;
            cp_async16(w_base + pr * 128 + slot * 16, src, ok);
        }
        asm volatile("cp.async.commit_group;\n");
    };

    load_stage(0, 0);
    load_stage(1, 32);
    load_stage(2, 64);

    const int a_lr_off = (lane & 8) + (lane & 7);
    const int a_cx     = (lane >> 4) & 1;
    const int b_lr_off = ((lane & 16) >> 1) + (lane & 7);
    const int b_cx     = (lane >> 3) & 1;

    const int NIT = 8;
#pragma unroll
    for (int it = 0; it < NIT; it++) {
        if (it <= NIT - 3)      asm volatile("cp.async.wait_group 2;\n");
        else if (it == NIT - 2) asm volatile("cp.async.wait_group 1;\n");
        else                    asm volatile("cp.async.wait_group 0;\n");
        __syncthreads();
        if (it + 3 < NIT) load_stage((it + 3) & 3, (it + 3) * 32);

        const unsigned a_base = smem_u + (it & 3) * 16384;
        const unsigned w_base = a_base + 8192;

#pragma unroll
        for (int kk = 0; kk < 2; kk++) {
            unsigned a[2][4], b[4][4];
#pragma unroll
            for (int mi = 0; mi < 2; mi++) {
                int lr = warp_m + mi * 16 + a_lr_off;
                int c  = kk * 2 + a_cx;
                int pr = lr >> 1;
                int slot = (c | ((lr & 1) << 2)) ^ (pr & 7);
                ldmatrix_x4(a[mi], a_base + pr * 128 + slot * 16);
            }
#pragma unroll
            for (int bi = 0; bi < 4; bi++) {
                int lr = warp_n + bi * 16 + b_lr_off;
                int c  = kk * 2 + b_cx;
                int pr = lr >> 1;
                int slot = (c | ((lr & 1) << 2)) ^ (pr & 7);
                ldmatrix_x4(b[bi], w_base + pr * 128 + slot * 16);
            }
#pragma unroll
            for (int mi = 0; mi < 2; mi++)
#pragma unroll
                for (int ni = 0; ni < 8; ni++) {
                    unsigned b0 = b[ni >> 1][(ni & 1) * 2];
                    unsigned b1 = b[ni >> 1][(ni & 1) * 2 + 1];
                    asm volatile(
                        "mma.sync.aligned.m16n8k16.row.col.f32.f16.f16.f32 "
                        "{%0,%1,%2,%3}, {%4,%5,%6,%7}, {%8,%9}, {%0,%1,%2,%3};"
                        : "+f"(acc[mi][ni][0]), "+f"(acc[mi][ni][1]),
                          "+f"(acc[mi][ni][2]), "+f"(acc[mi][ni][3])
                        : "r"(a[mi][0]), "r"(a[mi][1]), "r"(a[mi][2]), "r"(a[mi][3]),
                          "r"(b0), "r"(b1));
                }
        }
    }

    // epilogue
    const int g = lane >> 2;
    const int t = lane & 3;
    __half* Vh = reinterpret_cast<__half*>(g_valrep);
#pragma unroll
    for (int mi = 0; mi < 2; mi++) {
        int row0 = m0 + warp_m + mi * 16 + g;
#pragma unroll
        for (int ni = 0; ni < 8; ni++) {
            int col = n0 + warp_n + ni * 8 + t * 2;
            if (col < N) {
                float bx = bias[col], by = bias[col + 1];
                float v00 = acc[mi][ni][0] + bx, v01 = acc[mi][ni][1] + by;
                float v10 = acc[mi][ni][2] + bx, v11 = acc[mi][ni][3] + by;
                if (MODE == 1) {
                    int b  = row0 >= SEQ;
                    int s  = row0 - b * SEQ;
                    int h  = col >> 5;
                    int d  = col & 31;
                    size_t plane = (size_t)(b * 8 + h) * SEQP;
                    __half2 p0 = __floats2half2_rn(v00, v01);
                    __half2 p1 = __floats2half2_rn(v10, v11);
                    *reinterpret_cast<__half2*>(&Vh[(plane + s    ) * 32 + d]) = p0;
                    *reinterpret_cast<__half2*>(&Vh[(plane + s + 8) * 32 + d]) = p1;
                    *reinterpret_cast<__half2*>(&Vh[CPYB_H + (plane + s + 1) * 32 + d]) = p0;
                    *reinterpret_cast<__half2*>(&Vh[CPYB_H + (plane + s + 9) * 32 + d]) = p1;
                } else {
                    *reinterpret_cast<__half2*>(&g_offaw_h[(size_t)row0 * 288 + col]) =
                        __floats2half2_rn(v00, v01);
                    *reinterpret_cast<__half2*>(&g_offaw_h[(size_t)(row0 + 8) * 288 + col]) =
                        __floats2half2_rn(v10, v11);
                }
            }
        }
    }
}

// Merged value-proj (x<2) + offsets/aw-proj (x>=2) launch
__global__ void __launch_bounds__(256, 2) fused_proj_gemm(
    const __half* __restrict__ enc_h, const __half* __restrict__ valw,
    const float* __restrict__ valb,
    const __half* __restrict__ hid_h, const __half* __restrict__ obw,
    const float* __restrict__ obb)
{
    if (blockIdx.x < 2)
        hgemm_core<1>(enc_h, valw, valb, 256, blockIdx.x * 128);
    else
        hgemm_core<2>(hid_h, obw, obb, 288, (blockIdx.x - 2) * 128);
}

// ---------------------------------------------------------------------------
// FUSED sampler + output projection. Block = 128 queries.
// Phase S: 16 chunks of 8 queries; R7-proven sampler writes fp16 directly
//   into the GEMM's swizzled smem A-tile (slab h = head h; chunk c = lane).
// Phase G: 2 N-halves x 8 K-slabs of ldsm+mma; A from smem, W streamed via
//   2-stage cp.async ring (load issued AFTER the slab barrier => no hazard).
// ---------------------------------------------------------------------------
#define SMP_A    0            // 8 slabs x 8192 = 65536
#define SMP_W    65536        // 2 stages x 8192 = 16384
#define SMP_AW   81920        // 768 floats = 3072
#define SMP_OFF  84992        // 768 int2   = 6144
#define SMP_WT   91136        // 768 float4 = 12288
#define SM_FUSED 103424

#define QB 8
#define NSAMP (QB * HEADS * LEVELS * POINTS)   // 768

__global__ void __launch_bounds__(256) sample_outproj_kernel(
    const float* __restrict__ refp,
    const __half* __restrict__ outw,
    const float* __restrict__ outb,
    float* __restrict__ out)
{
    const unsigned smem_u = (unsigned)__cvta_generic_to_shared(smem_dyn);
    float*  s_aw  = reinterpret_cast<float*>(smem_dyn + SMP_AW);
    int2*   s_off = reinterpret_cast<int2*>(smem_dyn + SMP_OFF);
    float4* s_wt  = reinterpret_cast<float4*>(smem_dyn + SMP_WT);

    const int tid  = threadIdx.x;
    const int wid  = tid >> 5;
    const int lane = tid & 31;
    const int m0   = blockIdx.x * 128;

    // W slab loader: t = half*8 + s; W rows half*128 + r, k-cols s*32..+31
    auto loadW = [&](int stage, int t) {
        const int half = t >> 3, s = t & 7;
#pragma unroll
        for (int i = 0; i < 2; i++) {
            int idx = tid + i * 256;
            int r = idx >> 2, c = idx & 3;
            int pr = r >> 1;
            int slot = (c | ((r & 1) << 2)) ^ (pr & 7);
            cp_async16(smem_u + SMP_W + stage * 8192 + pr * 128 + slot * 16,
                       &outw[(size_t)(half * 128 + r) * 256 + s * 32 + c * 8], 16);
        }
        asm volatile("cp.async.commit_group;\n");
    };

    // prefetch first W slab; completes during sampling
    loadW(0, 0);

    // ======== Phase S: sampling, 16 chunks of 8 queries ========
    const int lvlW[3]     = {128, 64, 32};
    const int lvlStart[3] = {0, 16384, 20480};
    const uint4* __restrict__ VR = g_valrep;
    const int ll = tid & 7;

#pragma unroll 1
    for (int q8 = 0; q8 < 16; q8++) {
        const int bq0 = m0 + q8 * QB;

        // 1a: softmax per (q,h)
        if (tid < QB * HEADS) {
            const int bqi = tid >> 3;
            const int h   = tid & 7;
            const __half* awp = g_offaw_h + (size_t)(bq0 + bqi) * 288 + 192 + h * 12;
            float w[12];
            float mx = -1e30f;
#pragma unroll
            for (int j = 0; j < 12; j++) { w[j] = __half2float(awp[j]); mx = fmaxf(mx, w[j]); }
            float s = 0.f;
#pragma unroll
            for (int j = 0; j < 12; j++) { w[j] = __expf(w[j] - mx); s += w[j]; }
            const float invs = 1.f / s;
#pragma unroll
            for (int j = 0; j < 12; j++) s_aw[tid * 12 + j] = w[j] * invs;
        }
        __syncthreads();

        // 1b: per-sample params
#pragma unroll
        for (int i = 0; i < 3; i++) {
            const int sid = tid + i * 256;
            const int bqi = sid / 96;
            const int r   = sid - bqi * 96;
            const int h   = r / 12;
            const int lp  = r - h * 12;
            const int l   = lp >> 2;

            const int bq = bq0 + bqi;
            const int b  = (bq >= NQUERY) ? 1 : 0;
            const int Wl = lvlW[l];
            const float fW = (float)Wl;

            const __half2 oxy = *reinterpret_cast<const __half2*>(
                g_offaw_h + (size_t)bq * 288 + h * 24 + lp * 2);
            const float ox = __low2float(oxy);
            const float oy = __high2float(oxy);
            const float rx = refp[(size_t)bq * 6 + l * 2 + 0];
            const float ry = refp[(size_t)bq * 6 + l * 2 + 1];

            const float x = fmaf(rx, fW, ox) - 0.5f;
            const float y = fmaf(ry, fW, oy) - 0.5f;
            const float xf = floorf(x), yf = floorf(y);
            const float wx = x - xf,    wy = y - yf;
            const int x0 = (int)xf, y0 = (int)yf;

            const int xb = min(max(x0, 0), Wl - 1);
            float wxl = (x0 >= 0 && x0 < Wl) ? (1.f - wx) : ((x0 == -1) ? wx : 0.f);
            float wxr = (x0 >= 0 && x0 + 1 < Wl) ? wx : 0.f;
            const int y0c = min(max(y0, 0), Wl - 1);
            const int y1c = min(max(y0 + 1, 0), Wl - 1);
            float wy0 = (y0 >= 0 && y0 < Wl) ? (1.f - wy) : 0.f;
            float wy1 = (y0 + 1 >= 0 && y0 + 1 < Wl) ? wy : 0.f;

            const float ws = s_aw[(bqi * 8 + h) * 12 + lp];
            float4 wt;
            wt.x = ws * wy0 * wxl;
            wt.y = ws * wy0 * wxr;
            wt.z = ws * wy1 * wxl;
            wt.w = ws * wy1 * wxr;

            const int plane = (b * 8 + h) * SEQP;
            const int idx0  = lvlStart[l] + y0c * Wl + xb;
            const int idx1  = lvlStart[l] + y1c * Wl + xb;
            const int odd   = xb & 1;
            const int cbase = odd ? ((int)CPYB_U4 + 4) : 0;
            int2 off;
            off.x = cbase + (plane + idx0) * 4;
            off.y = cbase + (plane + idx1) * 4;

            s_off[sid] = off;
            s_wt[sid]  = wt;
        }
        __syncthreads();

        // 2: gather -> write swizzled A-tile rows q8*8..q8*8+7
#pragma unroll
        for (int pass = 0; pass < 2; pass++) {
            const int u   = (tid >> 3) + pass * 32;   // 0..63
            const int bqi = u >> 3;
            const int h   = u & 7;

            float acc[8];
#pragma unroll
            for (int c = 0; c < 8; c++) acc[c] = 0.f;

#pragma unroll
            for (int s12 = 0; s12 < 12; s12++) {
                const int sid = u * 12 + s12;
                const int2   off = s_off[sid];
                const float4 wt  = s_wt[sid];
                uint4 r0 = VR[off.x + ll];
                uint4 r1 = VR[off.y + ll];
                const __half2 wa2 = __float2half2_rn((ll & 4) ? wt.y : wt.x);
                const __half2 wb2 = __float2half2_rn((ll & 4) ? wt.w : wt.z);
                const __half2* p0 = reinterpret_cast<const __half2*>(&r0);
                const __half2* p1 = reinterpret_cast<const __half2*>(&r1);
#pragma unroll
                for (int j = 0; j < 4; j++) {
                    __half2 tt = __hfma2(p0[j], wa2, __hmul2(p1[j], wb2));
                    float2 ft = __half22float2(tt);
                    acc[2*j]   += ft.x;
                    acc[2*j+1] += ft.y;
                }
            }
#pragma unroll
            for (int c = 0; c < 8; c++)
                acc[c] += __shfl_xor_sync(0xffffffffu, acc[c], 4);

            if (ll < 4) {
                __half2 o0 = __floats2half2_rn(acc[0], acc[1]);
                __half2 o1 = __floats2half2_rn(acc[2], acc[3]);
                __half2 o2 = __floats2half2_rn(acc[4], acc[5]);
                __half2 o3 = __floats2half2_rn(acc[6], acc[7]);
                uint4 ov;
                ov.x = *reinterpret_cast<unsigned*>(&o0);
                ov.y = *reinterpret_cast<unsigned*>(&o1);
                ov.z = *reinterpret_cast<unsigned*>(&o2);
                ov.w = *reinterpret_cast<unsigned*>(&o3);
                // A slab h, row r = q8*8+bqi, chunk c = ll (8 halves)
                const int r  = q8 * QB + bqi;
                const int pr = r >> 1;
                const int slot = (ll | ((r & 1) << 2)) ^ (pr & 7);
                *reinterpret_cast<uint4*>(
                    smem_dyn + SMP_A + h * 8192 + pr * 128 + slot * 16) = ov;
            }
        }
        // no trailing sync needed: next 1a touches only s_aw (not read here);
        // the post-1a sync orders this phase vs next 1b's s_off writes.
    }

    // ======== Phase G: GEMM 128x256x256, A in smem, W streamed ========
    const int warp_m = (wid & 3) * 32;
    const int warp_n = (wid >> 2) * 64;
    const int a_lr_off = (lane & 8) + (lane & 7);
    const int a_cx     = (lane >> 4) & 1;
    const int b_lr_off = ((lane & 16) >> 1) + (lane & 7);
    const int b_cx     = (lane >> 3) & 1;
    const int g = lane >> 2;
    const int t2 = lane & 3;

#pragma unroll 1
    for (int half = 0; half < 2; half++) {
        float acc[2][8][4];
#pragma unroll
        for (int mi = 0; mi < 2; mi++)
#pragma unroll
            for (int ni = 0; ni < 8; ni++)
#pragma unroll
                for (int c = 0; c < 4; c++) acc[mi][ni][c] = 0.f;

#pragma unroll
        for (int s = 0; s < 8; s++) {
            const int t = half * 8 + s;
            asm volatile("cp.async.wait_group 0;\n");
            __syncthreads();
            if (t + 1 < 16) loadW((t + 1) & 1, t + 1);

            const unsigned a_base = smem_u + SMP_A + s * 8192;
            const unsigned w_base = smem_u + SMP_W + (t & 1) * 8192;

#pragma unroll
            for (int kk = 0; kk < 2; kk++) {
                unsigned a[2][4], b[4][4];
#pragma unroll
                for (int mi = 0; mi < 2; mi++) {
                    int lr = warp_m + mi * 16 + a_lr_off;
                    int c  = kk * 2 + a_cx;
                    int pr = lr >> 1;
                    int slot = (c | ((lr & 1) << 2)) ^ (pr & 7);
                    ldmatrix_x4(a[mi], a_base + pr * 128 + slot * 16);
                }
#pragma unroll
                for (int bi = 0; bi < 4; bi++) {
                    int lr = warp_n + bi * 16 + b_lr_off;
                    int c  = kk * 2 + b_cx;
                    int pr = lr >> 1;
                    int slot = (c | ((lr & 1) << 2)) ^ (pr & 7);
                    ldmatrix_x4(b[bi], w_base + pr * 128 + slot * 16);
                }
#pragma unroll
                for (int mi = 0; mi < 2; mi++)
#pragma unroll
                    for (int ni = 0; ni < 8; ni++) {
                        unsigned b0 = b[ni >> 1][(ni & 1) * 2];
                        unsigned b1 = b[ni >> 1][(ni & 1) * 2 + 1];
                        asm volatile(
                            "mma.sync.aligned.m16n8k16.row.col.f32.f16.f16.f32 "
                            "{%0,%1,%2,%3}, {%4,%5,%6,%7}, {%8,%9}, {%0,%1,%2,%3};"
                            : "+f"(acc[mi][ni][0]), "+f"(acc[mi][ni][1]),
                              "+f"(acc[mi][ni][2]), "+f"(acc[mi][ni][3])
                            : "r"(a[mi][0]), "r"(a[mi][1]), "r"(a[mi][2]), "r"(a[mi][3]),
                              "r"(b0), "r"(b1));
                    }
            }
        }

        // epilogue for this half (cols half*128 + 0..127)
#pragma unroll
        for (int mi = 0; mi < 2; mi++) {
            int row0 = m0 + warp_m + mi * 16 + g;
#pragma unroll
            for (int ni = 0; ni < 8; ni++) {
                int col = half * 128 + warp_n + ni * 8 + t2 * 2;
                float bx = outb[col], by = outb[col + 1];
                *reinterpret_cast<float2*>(&out[(size_t)row0 * 256 + col]) =
                    make_float2(acc[mi][ni][0] + bx, acc[mi][ni][1] + by);
                *reinterpret_cast<float2*>(&out[(size_t)(row0 + 8) * 256 + col]) =
                    make_float2(acc[mi][ni][2] + bx, acc[mi][ni][3] + by);
            }
        }
    }
}

// ---------------------------------------------------------------------------

extern "C" void kernel_launch(void* const* d_in, const int* in_sizes, int n_in,
                              void* d_out, int out_size)
{
    const float* hidden = (const float*)d_in[0];   // [B,Q,256]
    const float* enc    = (const float*)d_in[1];   // [B,S,256]
    const float* refp   = (const float*)d_in[2];   // [B,Q,L,2]
    // d_in[3] = spatial_shapes (static, hardcoded)
    const float* off_w  = (const float*)d_in[4];   // [192,256]
    const float* off_b  = (const float*)d_in[5];
    const float* aw_w   = (const float*)d_in[6];   // [96,256]
    const float* aw_b   = (const float*)d_in[7];
    const float* val_w  = (const float*)d_in[8];   // [256,256]
    const float* val_b  = (const float*)d_in[9];
    const float* out_w  = (const float*)d_in[10];  // [256,256]
    const float* out_b  = (const float*)d_in[11];
    float* out = (float*)d_out;

    __half *p_hid_h, *p_enc_h, *p_valw, *p_outw, *p_obw;
    float  *p_obb;
    cudaGetSymbolAddress((void**)&p_hid_h,  g_hidden_h);
    cudaGetSymbolAddress((void**)&p_enc_h,  g_enc_h);
    cudaGetSymbolAddress((void**)&p_valw,   g_valw_h);
    cudaGetSymbolAddress((void**)&p_outw,   g_outw_h);
    cudaGetSymbolAddress((void**)&p_obw,    g_obw_h);
    cudaGetSymbolAddress((void**)&p_obb,    g_obb);

    static int smem_set = 0;
    if (!smem_set) {
        cudaFuncSetAttribute(fused_proj_gemm,
                             cudaFuncAttributeMaxDynamicSharedMemorySize, 65536);
        cudaFuncSetAttribute(sample_outproj_kernel,
                             cudaFuncAttributeMaxDynamicSharedMemorySize, SM_FUSED);
        smem_set = 1;
    }

    const int MB = MROWS / 128;   // 336
    dim3 blk(256);

    // all fp32 -> fp16 conversions + bias concat in one launch
    f2h_mega<<<(SEG_AWW + 255) / 256, blk>>>(
        (const float4*)hidden, (const float4*)enc,
        (const float4*)val_w, (const float4*)out_w,
        (const float4*)off_w, (const float4*)aw_w,
        off_b, aw_b);

    // merged: value projection (x<2) + fused off/aw projection (x>=2)
    fused_proj_gemm<<<dim3(5, MB), blk, 65536>>>(p_enc_h, p_valw, val_b,
                                                 p_hid_h, p_obw, p_obb);

    // fused deformable sampling + output projection
    sample_outproj_kernel<<<MB, blk, SM_FUSED>>>(refp, p_outw, out_b, out);
}

// round 15
// speedup vs baseline: 1.4842x; 1.4842x over previous
#include <cuda_runtime.h>
#include <cuda_fp16.h>
#include <math.h>

// Problem constants (static in the reference)
#define EMBED   256
#define HEADS   8
#define LEVELS  3
#define POINTS  4
#define DHEAD   32
#define BATCH   2
#define SEQ     21504          // 128*128 + 64*64 + 32*32
#define NQUERY  21504
#define MROWS   (BATCH * NQUERY)   // 43008

#define SEQP    (SEQ + 2)                 // padded pixels per (b,h) plane
#define NPLANE  (BATCH * HEADS)           // 16
#define CPYB_H  ((size_t)NPLANE * SEQP * DHEAD)   // halves per copy
#define CPYB_U4 (CPYB_H / 8)                      // uint4 per copy

// Scratch (device globals; no allocation allowed)
__device__ uint4  g_valrep[2 * CPYB_U4];          // fp16 value [copy][B,H,Sp,D]
__device__ __half g_hidden_h[(size_t)MROWS * EMBED];
__device__ __half g_enc_h   [(size_t)BATCH * SEQ * EMBED];
__device__ __half g_msda_h  [(size_t)MROWS * EMBED];
__device__ __half g_valw_h  [256 * 256];
__device__ __half g_outw_h  [256 * 256];
__device__ __half g_obw_h   [288 * 256];          // off(192) + aw(96) weights
__device__ float  g_obb     [288];                // concat bias
__device__ __half g_offaw_h [(size_t)MROWS * 288];// fused off+aw output (fp16)

// ---------------------------------------------------------------------------
// Mega fp32->fp16 conversion: hidden, enc, val_w, out_w, off_w|aw_w concat.
// ---------------------------------------------------------------------------
#define SEG_H   1376256                 // hidden uint4
#define SEG_E   (SEG_H + 1376256)       // enc
#define SEG_VW  (SEG_E + 8192)
#define SEG_OW  (SEG_VW + 8192)
#define SEG_OFW (SEG_OW + 6144)
#define SEG_AWW (SEG_OFW + 3072)        // total 2778112

__global__ void f2h_mega(const float4* __restrict__ hidden,
                         const float4* __restrict__ enc,
                         const float4* __restrict__ valw,
                         const float4* __restrict__ outw,
                         const float4* __restrict__ offw,
                         const float4* __restrict__ aww,
                         const float*  __restrict__ offb,
                         const float*  __restrict__ awb)
{
    const int gid = blockIdx.x * blockDim.x + threadIdx.x;
    if (gid < 288)
        g_obb[gid] = (gid < 192) ? offb[gid] : awb[gid - 192];
    if (gid >= SEG_AWW) return;

    const float4* src;
    uint4* dst;
    int idx;
    if (gid < SEG_H)        { src = hidden; dst = (uint4*)g_hidden_h; idx = gid; }
    else if (gid < SEG_E)   { src = enc;    dst = (uint4*)g_enc_h;    idx = gid - SEG_H; }
    else if (gid < SEG_VW)  { src = valw;   dst = (uint4*)g_valw_h;   idx = gid - SEG_E; }
    else if (gid < SEG_OW)  { src = outw;   dst = (uint4*)g_outw_h;   idx = gid - SEG_VW; }
    else if (gid < SEG_OFW) { src = offw;   dst = (uint4*)g_obw_h;    idx = gid - SEG_OW; }
    else                    { src = aww;    dst = (uint4*)g_obw_h + 6144; idx = gid - SEG_OFW; }

    float4 f0 = src[2 * idx];
    float4 f1 = src[2 * idx + 1];
    __half2 h0 = __floats2half2_rn(f0.x, f0.y);
    __half2 h1 = __floats2half2_rn(f0.z, f0.w);
    __half2 h2 = __floats2half2_rn(f1.x, f1.y);
    __half2 h3 = __floats2half2_rn(f1.z, f1.w);
    uint4 o;
    o.x = *reinterpret_cast<unsigned*>(&h0);
    o.y = *reinterpret_cast<unsigned*>(&h1);
    o.z = *reinterpret_cast<unsigned*>(&h2);
    o.w = *reinterpret_cast<unsigned*>(&h3);
    dst[idx] = o;
}

__device__ __forceinline__ void cp_async16(unsigned smem_addr, const void* gptr, int src_size) {
    asm volatile("cp.async.cg.shared.global [%0], [%1], 16, %2;\n"
                 :: "r"(smem_addr), "l"(gptr), "r"(src_size));
}
__device__ __forceinline__ void ldmatrix_x4(unsigned* r, unsigned addr) {
    asm volatile("ldmatrix.sync.aligned.m8n8.x4.shared.b16 {%0,%1,%2,%3}, [%4];"
                 : "=r"(r[0]), "=r"(r[1]), "=r"(r[2]), "=r"(r[3]) : "r"(addr));
}

// ---------------------------------------------------------------------------
// FP16 GEMM core (R11-proven): C[M,N] = A[M,256] * W[N,256]^T + bias[N]
// BM=128, BN=128, BK=32, 4-stage cp.async (16KB/stage, 64KB dynamic smem).
// MODE: 0 = fp32 C, 1 = value replicated fp16 (g_valrep), 2 = fp16 row-288
// ---------------------------------------------------------------------------
extern __shared__ char smem_dyn[];

template<int MODE>
__device__ __forceinline__ void hgemm_core(
    const __half* __restrict__ A, const __half* __restrict__ W,
    const float* __restrict__ bias, float* __restrict__ C,
    int N, int n0)
{
    const int K = 256;
    const unsigned smem_u = (unsigned)__cvta_generic_to_shared(smem_dyn);

    const int tid  = threadIdx.x;
    const int wid  = tid >> 5;
    const int lane = tid & 31;

    const int m0 = blockIdx.y * 128;
    const int warp_m = (wid & 3) * 32;
    const int warp_n = (wid >> 2) * 64;

    float acc[2][8][4];
#pragma unroll
    for (int mi = 0; mi < 2; mi++)
#pragma unroll
        for (int ni = 0; ni < 8; ni++)
#pragma unroll
            for (int c = 0; c < 4; c++) acc[mi][ni][c] = 0.f;

    auto load_stage = [&](int stage, int k0) {
        const unsigned a_base = smem_u + stage * 16384;
        const unsigned w_base = a_base + 8192;
#pragma unroll
        for (int i = 0; i < 2; i++) {
            int idx = tid + i * 256;
            int r = idx >> 2, c = idx & 3;
            int pr = r >> 1;
            int slot = (c | ((r & 1) << 2)) ^ (pr & 7);
            cp_async16(a_base + pr * 128 + slot * 16,
                       &A[(size_t)(m0 + r) * K + k0 + c * 8], 16);
        }
#pragma unroll
        for (int i = 0; i < 2; i++) {
            int idx = tid + i * 256;
            int r = idx >> 2, c = idx & 3;
            int pr = r >> 1;
            int slot = (c | ((r & 1) << 2)) ^ (pr & 7);
            int n  = n0 + r;
            int ok = (n < N) ? 16 : 0;
            const __half* src = (n < N) ? &W[(size_t)n * K + k0 + c * 8] : W;
            cp_async16(w_base + pr * 128 + slot * 16, src, ok);
        }
        asm volatile("cp.async.commit_group;\n");
    };

    load_stage(0, 0);
    load_stage(1, 32);
    load_stage(2, 64);

    const int a_lr_off = (lane & 8) + (lane & 7);
    const int a_cx     = (lane >> 4) & 1;
    const int b_lr_off = ((lane & 16) >> 1) + (lane & 7);
    const int b_cx     = (lane >> 3) & 1;

    const int NIT = 8;
#pragma unroll
    for (int it = 0; it < NIT; it++) {
        if (it <= NIT - 3)      asm volatile("cp.async.wait_group 2;\n");
        else if (it == NIT - 2) asm volatile("cp.async.wait_group 1;\n");
        else                    asm volatile("cp.async.wait_group 0;\n");
        __syncthreads();
        if (it + 3 < NIT) load_stage((it + 3) & 3, (it + 3) * 32);

        const unsigned a_base = smem_u + (it & 3) * 16384;
        const unsigned w_base = a_base + 8192;

#pragma unroll
        for (int kk = 0; kk < 2; kk++) {
            unsigned a[2][4], b[4][4];
#pragma unroll
            for (int mi = 0; mi < 2; mi++) {
                int lr = warp_m + mi * 16 + a_lr_off;
                int c  = kk * 2 + a_cx;
                int pr = lr >> 1;
                int slot = (c | ((lr & 1) << 2)) ^ (pr & 7);
                ldmatrix_x4(a[mi], a_base + pr * 128 + slot * 16);
            }
#pragma unroll
            for (int bi = 0; bi < 4; bi++) {
                int lr = warp_n + bi * 16 + b_lr_off;
                int c  = kk * 2 + b_cx;
                int pr = lr >> 1;
                int slot = (c | ((lr & 1) << 2)) ^ (pr & 7);
                ldmatrix_x4(b[bi], w_base + pr * 128 + slot * 16);
            }
#pragma unroll
            for (int mi = 0; mi < 2; mi++)
#pragma unroll
                for (int ni = 0; ni < 8; ni++) {
                    unsigned b0 = b[ni >> 1][(ni & 1) * 2];
                    unsigned b1 = b[ni >> 1][(ni & 1) * 2 + 1];
                    asm volatile(
                        "mma.sync.aligned.m16n8k16.row.col.f32.f16.f16.f32 "
                        "{%0,%1,%2,%3}, {%4,%5,%6,%7}, {%8,%9}, {%0,%1,%2,%3};"
                        : "+f"(acc[mi][ni][0]), "+f"(acc[mi][ni][1]),
                          "+f"(acc[mi][ni][2]), "+f"(acc[mi][ni][3])
                        : "r"(a[mi][0]), "r"(a[mi][1]), "r"(a[mi][2]), "r"(a[mi][3]),
                          "r"(b0), "r"(b1));
                }
        }
    }

    // epilogue
    const int g = lane >> 2;
    const int t = lane & 3;
    __half* Vh = reinterpret_cast<__half*>(g_valrep);
#pragma unroll
    for (int mi = 0; mi < 2; mi++) {
        int row0 = m0 + warp_m + mi * 16 + g;
#pragma unroll
        for (int ni = 0; ni < 8; ni++) {
            int col = n0 + warp_n + ni * 8 + t * 2;
            if (col < N) {
                float bx = bias[col], by = bias[col + 1];
                float v00 = acc[mi][ni][0] + bx, v01 = acc[mi][ni][1] + by;
                float v10 = acc[mi][ni][2] + bx, v11 = acc[mi][ni][3] + by;
                if (MODE == 1) {
                    int b  = row0 >= SEQ;
                    int s  = row0 - b * SEQ;
                    int h  = col >> 5;
                    int d  = col & 31;
                    size_t plane = (size_t)(b * 8 + h) * SEQP;
                    __half2 p0 = __floats2half2_rn(v00, v01);
                    __half2 p1 = __floats2half2_rn(v10, v11);
                    *reinterpret_cast<__half2*>(&Vh[(plane + s    ) * 32 + d]) = p0;
                    *reinterpret_cast<__half2*>(&Vh[(plane + s + 8) * 32 + d]) = p1;
                    *reinterpret_cast<__half2*>(&Vh[CPYB_H + (plane + s + 1) * 32 + d]) = p0;
                    *reinterpret_cast<__half2*>(&Vh[CPYB_H + (plane + s + 9) * 32 + d]) = p1;
                } else if (MODE == 2) {
                    *reinterpret_cast<__half2*>(&g_offaw_h[(size_t)row0 * 288 + col]) =
                        __floats2half2_rn(v00, v01);
                    *reinterpret_cast<__half2*>(&g_offaw_h[(size_t)(row0 + 8) * 288 + col]) =
                        __floats2half2_rn(v10, v11);
                } else {
                    *reinterpret_cast<float2*>(&C[(size_t)row0 * N + col]) =
                        make_float2(v00, v01);
                    *reinterpret_cast<float2*>(&C[(size_t)(row0 + 8) * N + col]) =
                        make_float2(v10, v11);
                }
            }
        }
    }
}

// Merged value-proj (x<2) + offsets/aw-proj (x>=2) launch
__global__ void __launch_bounds__(256, 2) fused_proj_gemm(
    const __half* __restrict__ enc_h, const __half* __restrict__ valw,
    const float* __restrict__ valb,
    const __half* __restrict__ hid_h, const __half* __restrict__ obw,
    const float* __restrict__ obb)
{
    if (blockIdx.x < 2)
        hgemm_core<1>(enc_h, valw, valb, nullptr, 256, blockIdx.x * 128);
    else
        hgemm_core<2>(hid_h, obw, obb, nullptr, 288, (blockIdx.x - 2) * 128);
}

__global__ void __launch_bounds__(256, 2) out_proj_gemm(
    const __half* __restrict__ msda, const __half* __restrict__ outw,
    const float* __restrict__ outb, float* __restrict__ out)
{
    hgemm_core<0>(msda, outw, outb, out, 256, blockIdx.x * 128);
}

// ---------------------------------------------------------------------------
// Deformable sampling. Value fp16 [copy][B,H,Sp,D]; x-pixel pair = one
// aligned 128B load (copy picked by xb parity). Unit = 8 lanes: lanes 0-3
// pixel xb, 4-7 pixel xb+1; shfl_xor(4)-add.
// Per-sample params packed into ONE int4 {off0, off1, half2(w0l,w1l),
// half2(w0r,w1r)} -> single LDS.128 broadcast (was int2 + float4 = 2 LDS).
// ---------------------------------------------------------------------------
#define QB 8
#define NSAMP (QB * HEADS * LEVELS * POINTS)   // 768

__global__ void __launch_bounds__(256) msda_sample_kernel(
    const float* __restrict__ refp)
{
    __shared__ float s_aw[QB * HEADS * 12];
    __shared__ int4  s_pack[NSAMP];   // {off0, off1, wL(half2), wR(half2)}

    const int tid = threadIdx.x;
    const int bq0 = blockIdx.x * QB;

    // Phase 1a: softmax once per (q, h); fp16 logits at g_offaw_h[.., 192+]
    if (tid < QB * HEADS) {
        const int bqi = tid >> 3;
        const int h   = tid & 7;
        const __half* awp = g_offaw_h + (size_t)(bq0 + bqi) * 288 + 192 + h * 12;
        float w[12];
        float mx = -1e30f;
#pragma unroll
        for (int j = 0; j < 12; j++) { w[j] = __half2float(awp[j]); mx = fmaxf(mx, w[j]); }
        float s = 0.f;
#pragma unroll
        for (int j = 0; j < 12; j++) { w[j] = __expf(w[j] - mx); s += w[j]; }
        const float invs = 1.f / s;
#pragma unroll
        for (int j = 0; j < 12; j++) s_aw[tid * 12 + j] = w[j] * invs;
    }
    __syncthreads();

    // Phase 1b: per-sample params (3 samples per thread)
    const int lvlW[3]     = {128, 64, 32};
    const int lvlStart[3] = {0, 16384, 20480};
#pragma unroll
    for (int i = 0; i < 3; i++) {
        const int sid = tid + i * 256;
        const int bqi = sid / 96;
        const int r   = sid - bqi * 96;
        const int h   = r / 12;
        const int lp  = r - h * 12;
        const int l   = lp >> 2;

        const int bq = bq0 + bqi;
        const int b  = (bq >= NQUERY) ? 1 : 0;
        const int Wl = lvlW[l];
        const float fW = (float)Wl;

        const __half2 oxy = *reinterpret_cast<const __half2*>(
            g_offaw_h + (size_t)bq * 288 + h * 24 + lp * 2);
        const float ox = __low2float(oxy);
        const float oy = __high2float(oxy);
        const float rx = refp[(size_t)bq * 6 + l * 2 + 0];
        const float ry = refp[(size_t)bq * 6 + l * 2 + 1];

        const float x = fmaf(rx, fW, ox) - 0.5f;
        const float y = fmaf(ry, fW, oy) - 0.5f;
        const float xf = floorf(x), yf = floorf(y);
        const float wx = x - xf,    wy = y - yf;
        const int x0 = (int)xf, y0 = (int)yf;

        const int xb = min(max(x0, 0), Wl - 1);
        float wxl = (x0 >= 0 && x0 < Wl) ? (1.f - wx) : ((x0 == -1) ? wx : 0.f);
        float wxr = (x0 >= 0 && x0 + 1 < Wl) ? wx : 0.f;
        const int y0c = min(max(y0, 0), Wl - 1);
        const int y1c = min(max(y0 + 1, 0), Wl - 1);
        float wy0 = (y0 >= 0 && y0 < Wl) ? (1.f - wy) : 0.f;
        float wy1 = (y0 + 1 >= 0 && y0 + 1 < Wl) ? wy : 0.f;

        const float ws = s_aw[(bqi * 8 + h) * 12 + lp];
        // left side (rows 0,1), right side (rows 0,1) — rounded to fp16 here,
        // identical to the fp16 rounding previously done in phase 2.
        __half2 wL = __floats2half2_rn(ws * wy0 * wxl, ws * wy1 * wxl);
        __half2 wR = __floats2half2_rn(ws * wy0 * wxr, ws * wy1 * wxr);

        const int plane = (b * 8 + h) * SEQP;
        const int idx0  = lvlStart[l] + y0c * Wl + xb;
        const int idx1  = lvlStart[l] + y1c * Wl + xb;
        const int odd   = xb & 1;
        const int cbase = odd ? ((int)CPYB_U4 + 4) : 0;   // +1 pixel in copy B
        int4 pk;
        pk.x = cbase + (plane + idx0) * 4;
        pk.y = cbase + (plane + idx1) * 4;
        pk.z = *reinterpret_cast<int*>(&wL);
        pk.w = *reinterpret_cast<int*>(&wR);
        s_pack[sid] = pk;
    }
    __syncthreads();

    // Phase 2: gather. 2 passes x 32 units x 8 lanes.
    const uint4* __restrict__ VR = g_valrep;
    const int ll = tid & 7;
#pragma unroll
    for (int pass = 0; pass < 2; pass++) {
        const int u   = (tid >> 3) + pass * 32;   // 0..63
        const int bqi = u >> 3;
        const int h   = u & 7;

        float acc[8];
#pragma unroll
        for (int c = 0; c < 8; c++) acc[c] = 0.f;

#pragma unroll
        for (int s12 = 0; s12 < 12; s12++) {
            const int sid = u * 12 + s12;
            const int4 pk = s_pack[sid];      // single LDS.128 broadcast
            uint4 r0 = VR[pk.x + ll];
            uint4 r1 = VR[pk.y + ll];
            const int wsel = (ll & 4) ? pk.w : pk.z;   // register select
            const __half2 wpair = *reinterpret_cast<const __half2*>(&wsel);
            const __half2 wa2 = __half2half2(__low2half(wpair));   // row0 wt
            const __half2 wb2 = __half2half2(__high2half(wpair));  // row1 wt
            const __half2* p0 = reinterpret_cast<const __half2*>(&r0);
            const __half2* p1 = reinterpret_cast<const __half2*>(&r1);
#pragma unroll
            for (int j = 0; j < 4; j++) {
                __half2 tt = __hfma2(p0[j], wa2, __hmul2(p1[j], wb2));
                float2 ft = __half22float2(tt);
                acc[2*j]   += ft.x;
                acc[2*j+1] += ft.y;
            }
        }
#pragma unroll
        for (int c = 0; c < 8; c++)
            acc[c] += __shfl_xor_sync(0xffffffffu, acc[c], 4);

        if (ll < 4) {
            __half2 o0 = __floats2half2_rn(acc[0], acc[1]);
            __half2 o1 = __floats2half2_rn(acc[2], acc[3]);
            __half2 o2 = __floats2half2_rn(acc[4], acc[5]);
            __half2 o3 = __floats2half2_rn(acc[6], acc[7]);
            uint4 ov;
            ov.x = *reinterpret_cast<unsigned*>(&o0);
            ov.y = *reinterpret_cast<unsigned*>(&o1);
            ov.z = *reinterpret_cast<unsigned*>(&o2);
            ov.w = *reinterpret_cast<unsigned*>(&o3);
            uint4* outp = reinterpret_cast<uint4*>(g_msda_h)
                        + (size_t)(bq0 + bqi) * 32 + h * 4 + ll;
            *outp = ov;
        }
    }
}

// ---------------------------------------------------------------------------

extern "C" void kernel_launch(void* const* d_in, const int* in_sizes, int n_in,
                              void* d_out, int out_size)
{
    const float* hidden = (const float*)d_in[0];   // [B,Q,256]
    const float* enc    = (const float*)d_in[1];   // [B,S,256]
    const float* refp   = (const float*)d_in[2];   // [B,Q,L,2]
    // d_in[3] = spatial_shapes (static, hardcoded)
    const float* off_w  = (const float*)d_in[4];   // [192,256]
    const float* off_b  = (const float*)d_in[5];
    const float* aw_w   = (const float*)d_in[6];   // [96,256]
    const float* aw_b   = (const float*)d_in[7];
    const float* val_w  = (const float*)d_in[8];   // [256,256]
    const float* val_b  = (const float*)d_in[9];
    const float* out_w  = (const float*)d_in[10];  // [256,256]
    const float* out_b  = (const float*)d_in[11];
    float* out = (float*)d_out;

    __half *p_hid_h, *p_enc_h, *p_msda_h, *p_valw, *p_outw, *p_obw;
    float  *p_obb;
    cudaGetSymbolAddress((void**)&p_hid_h,  g_hidden_h);
    cudaGetSymbolAddress((void**)&p_enc_h,  g_enc_h);
    cudaGetSymbolAddress((void**)&p_msda_h, g_msda_h);
    cudaGetSymbolAddress((void**)&p_valw,   g_valw_h);
    cudaGetSymbolAddress((void**)&p_outw,   g_outw_h);
    cudaGetSymbolAddress((void**)&p_obw,    g_obw_h);
    cudaGetSymbolAddress((void**)&p_obb,    g_obb);

    static int smem_set = 0;
    const int SMEM_BYTES = 65536;
    if (!smem_set) {
        cudaFuncSetAttribute(fused_proj_gemm,
                             cudaFuncAttributeMaxDynamicSharedMemorySize, SMEM_BYTES);
        cudaFuncSetAttribute(out_proj_gemm,
                             cudaFuncAttributeMaxDynamicSharedMemorySize, SMEM_BYTES);
        smem_set = 1;
    }

    const int MB = MROWS / 128;   // 336
    dim3 blk(256);

    // all fp32 -> fp16 conversions + bias concat in one launch
    f2h_mega<<<(SEG_AWW + 255) / 256, blk>>>(
        (const float4*)hidden, (const float4*)enc,
        (const float4*)val_w, (const float4*)out_w,
        (const float4*)off_w, (const float4*)aw_w,
        off_b, aw_b);

    // merged: value projection (x<2) + fused off/aw projection (x>=2)
    fused_proj_gemm<<<dim3(5, MB), blk, SMEM_BYTES>>>(p_enc_h, p_valw, val_b,
                                                      p_hid_h, p_obw, p_obb);

    // deformable sampling -> fp16 msda
    msda_sample_kernel<<<MROWS / QB, blk>>>(refp);

    // output projection (fp32 out to d_out)
    out_proj_gemm<<<dim3(2, MB), blk, SMEM_BYTES>>>(p_msda_h, p_outw, out_b, out);
}

// round 16
// speedup vs baseline: 1.5221x; 1.0256x over previous
#include <cuda_runtime.h>
#include <cuda_fp16.h>
#include <math.h>

// Problem constants (static in the reference)
#define EMBED   256
#define HEADS   8
#define LEVELS  3
#define POINTS  4
#define DHEAD   32
#define BATCH   2
#define SEQ     21504          // 128*128 + 64*64 + 32*32
#define NQUERY  21504
#define MROWS   (BATCH * NQUERY)   // 43008

#define SEQP    (SEQ + 2)                 // padded pixels per (b,h) plane
#define NPLANE  (BATCH * HEADS)           // 16
#define CPYB_H  ((size_t)NPLANE * SEQP * DHEAD)   // halves per copy
#define CPYB_U4 (CPYB_H / 8)                      // uint4 per copy

// Scratch (device globals; no allocation allowed)
__device__ uint4  g_valrep[2 * CPYB_U4];          // fp16 value [copy][B,H,Sp,D]
__device__ __half g_hidden_h[(size_t)MROWS * EMBED];
__device__ __half g_enc_h   [(size_t)BATCH * SEQ * EMBED];
__device__ __half g_msda_h  [(size_t)MROWS * EMBED];
__device__ __half g_valw_h  [256 * 256];
__device__ __half g_outw_h  [256 * 256];
__device__ __half g_obw_h   [288 * 256];          // off(192) + aw(96) weights
__device__ float  g_obb     [288];                // concat bias
__device__ __half g_offaw_h [(size_t)MROWS * 288];// fused off+aw output (fp16)

// ---------------------------------------------------------------------------
// Mega fp32->fp16 conversion: hidden, enc, val_w, out_w, off_w|aw_w concat.
// ---------------------------------------------------------------------------
#define SEG_H   1376256                 // hidden uint4
#define SEG_E   (SEG_H + 1376256)       // enc
#define SEG_VW  (SEG_E + 8192)
#define SEG_OW  (SEG_VW + 8192)
#define SEG_OFW (SEG_OW + 6144)
#define SEG_AWW (SEG_OFW + 3072)        // total 2778112

__global__ void f2h_mega(const float4* __restrict__ hidden,
                         const float4* __restrict__ enc,
                         const float4* __restrict__ valw,
                         const float4* __restrict__ outw,
                         const float4* __restrict__ offw,
                         const float4* __restrict__ aww,
                         const float*  __restrict__ offb,
                         const float*  __restrict__ awb)
{
    const int gid = blockIdx.x * blockDim.x + threadIdx.x;
    if (gid < 288)
        g_obb[gid] = (gid < 192) ? offb[gid] : awb[gid - 192];
    if (gid >= SEG_AWW) return;

    const float4* src;
    uint4* dst;
    int idx;
    if (gid < SEG_H)        { src = hidden; dst = (uint4*)g_hidden_h; idx = gid; }
    else if (gid < SEG_E)   { src = enc;    dst = (uint4*)g_enc_h;    idx = gid - SEG_H; }
    else if (gid < SEG_VW)  { src = valw;   dst = (uint4*)g_valw_h;   idx = gid - SEG_E; }
    else if (gid < SEG_OW)  { src = outw;   dst = (uint4*)g_outw_h;   idx = gid - SEG_VW; }
    else if (gid < SEG_OFW) { src = offw;   dst = (uint4*)g_obw_h;    idx = gid - SEG_OW; }
    else                    { src = aww;    dst = (uint4*)g_obw_h + 6144; idx = gid - SEG_OFW; }

    float4 f0 = src[2 * idx];
    float4 f1 = src[2 * idx + 1];
    __half2 h0 = __floats2half2_rn(f0.x, f0.y);
    __half2 h1 = __floats2half2_rn(f0.z, f0.w);
    __half2 h2 = __floats2half2_rn(f1.x, f1.y);
    __half2 h3 = __floats2half2_rn(f1.z, f1.w);
    uint4 o;
    o.x = *reinterpret_cast<unsigned*>(&h0);
    o.y = *reinterpret_cast<unsigned*>(&h1);
    o.z = *reinterpret_cast<unsigned*>(&h2);
    o.w = *reinterpret_cast<unsigned*>(&h3);
    dst[idx] = o;
}

__device__ __forceinline__ void cp_async16(unsigned smem_addr, const void* gptr, int src_size) {
    asm volatile("cp.async.cg.shared.global [%0], [%1], 16, %2;\n"
                 :: "r"(smem_addr), "l"(gptr), "r"(src_size));
}
__device__ __forceinline__ void ldmatrix_x4(unsigned* r, unsigned addr) {
    asm volatile("ldmatrix.sync.aligned.m8n8.x4.shared.b16 {%0,%1,%2,%3}, [%4];"
                 : "=r"(r[0]), "=r"(r[1]), "=r"(r[2]), "=r"(r[3]) : "r"(addr));
}

// ---------------------------------------------------------------------------
// FP16 GEMM core (R11-proven): C[M,N] = A[M,256] * W[N,256]^T + bias[N]
// BM=128, BN=128, BK=32, 4-stage cp.async (16KB/stage, 64KB dynamic smem).
// MODE: 0 = fp32 C, 1 = value replicated fp16 (g_valrep), 2 = fp16 row-288
// ---------------------------------------------------------------------------
extern __shared__ char smem_dyn[];

template<int MODE>
__device__ __forceinline__ void hgemm_core(
    const __half* __restrict__ A, const __half* __restrict__ W,
    const float* __restrict__ bias, float* __restrict__ C,
    int N, int n0)
{
    const int K = 256;
    const unsigned smem_u = (unsigned)__cvta_generic_to_shared(smem_dyn);

    const int tid  = threadIdx.x;
    const int wid  = tid >> 5;
    const int lane = tid & 31;

    const int m0 = blockIdx.y * 128;
    const int warp_m = (wid & 3) * 32;
    const int warp_n = (wid >> 2) * 64;

    float acc[2][8][4];
#pragma unroll
    for (int mi = 0; mi < 2; mi++)
#pragma unroll
        for (int ni = 0; ni < 8; ni++)
#pragma unroll
            for (int c = 0; c < 4; c++) acc[mi][ni][c] = 0.f;

    auto load_stage = [&](int stage, int k0) {
        const unsigned a_base = smem_u + stage * 16384;
        const unsigned w_base = a_base + 8192;
#pragma unroll
        for (int i = 0; i < 2; i++) {
            int idx = tid + i * 256;
            int r = idx >> 2, c = idx & 3;
            int pr = r >> 1;
            int slot = (c | ((r & 1) << 2)) ^ (pr & 7);
            cp_async16(a_base + pr * 128 + slot * 16,
                       &A[(size_t)(m0 + r) * K + k0 + c * 8], 16);
        }
#pragma unroll
        for (int i = 0; i < 2; i++) {
            int idx = tid + i * 256;
            int r = idx >> 2, c = idx & 3;
            int pr = r >> 1;
            int slot = (c | ((r & 1) << 2)) ^ (pr & 7);
            int n  = n0 + r;
            int ok = (n < N) ? 16 : 0;
            const __half* src = (n < N) ? &W[(size_t)n * K + k0 + c * 8] : W;
            cp_async16(w_base + pr * 128 + slot * 16, src, ok);
        }
        asm volatile("cp.async.commit_group;\n");
    };

    load_stage(0, 0);
    load_stage(1, 32);
    load_stage(2, 64);

    const int a_lr_off = (lane & 8) + (lane & 7);
    const int a_cx     = (lane >> 4) & 1;
    const int b_lr_off = ((lane & 16) >> 1) + (lane & 7);
    const int b_cx     = (lane >> 3) & 1;

    const int NIT = 8;
#pragma unroll
    for (int it = 0; it < NIT; it++) {
        if (it <= NIT - 3)      asm volatile("cp.async.wait_group 2;\n");
        else if (it == NIT - 2) asm volatile("cp.async.wait_group 1;\n");
        else                    asm volatile("cp.async.wait_group 0;\n");
        __syncthreads();
        if (it + 3 < NIT) load_stage((it + 3) & 3, (it + 3) * 32);

        const unsigned a_base = smem_u + (it & 3) * 16384;
        const unsigned w_base = a_base + 8192;

#pragma unroll
        for (int kk = 0; kk < 2; kk++) {
            unsigned a[2][4], b[4][4];
#pragma unroll
            for (int mi = 0; mi < 2; mi++) {
                int lr = warp_m + mi * 16 + a_lr_off;
                int c  = kk * 2 + a_cx;
                int pr = lr >> 1;
                int slot = (c | ((lr & 1) << 2)) ^ (pr & 7);
                ldmatrix_x4(a[mi], a_base + pr * 128 + slot * 16);
            }
#pragma unroll
            for (int bi = 0; bi < 4; bi++) {
                int lr = warp_n + bi * 16 + b_lr_off;
                int c  = kk * 2 + b_cx;
                int pr = lr >> 1;
                int slot = (c | ((lr & 1) << 2)) ^ (pr & 7);
                ldmatrix_x4(b[bi], w_base + pr * 128 + slot * 16);
            }
#pragma unroll
            for (int mi = 0; mi < 2; mi++)
#pragma unroll
                for (int ni = 0; ni < 8; ni++) {
                    unsigned b0 = b[ni >> 1][(ni & 1) * 2];
                    unsigned b1 = b[ni >> 1][(ni & 1) * 2 + 1];
                    asm volatile(
                        "mma.sync.aligned.m16n8k16.row.col.f32.f16.f16.f32 "
                        "{%0,%1,%2,%3}, {%4,%5,%6,%7}, {%8,%9}, {%0,%1,%2,%3};"
                        : "+f"(acc[mi][ni][0]), "+f"(acc[mi][ni][1]),
                          "+f"(acc[mi][ni][2]), "+f"(acc[mi][ni][3])
                        : "r"(a[mi][0]), "r"(a[mi][1]), "r"(a[mi][2]), "r"(a[mi][3]),
                          "r"(b0), "r"(b1));
                }
        }
    }

    // epilogue
    const int g = lane >> 2;
    const int t = lane & 3;
    __half* Vh = reinterpret_cast<__half*>(g_valrep);
#pragma unroll
    for (int mi = 0; mi < 2; mi++) {
        int row0 = m0 + warp_m + mi * 16 + g;
#pragma unroll
        for (int ni = 0; ni < 8; ni++) {
            int col = n0 + warp_n + ni * 8 + t * 2;
            if (col < N) {
                float bx = bias[col], by = bias[col + 1];
                float v00 = acc[mi][ni][0] + bx, v01 = acc[mi][ni][1] + by;
                float v10 = acc[mi][ni][2] + bx, v11 = acc[mi][ni][3] + by;
                if (MODE == 1) {
                    int b  = row0 >= SEQ;
                    int s  = row0 - b * SEQ;
                    int h  = col >> 5;
                    int d  = col & 31;
                    size_t plane = (size_t)(b * 8 + h) * SEQP;
                    __half2 p0 = __floats2half2_rn(v00, v01);
                    __half2 p1 = __floats2half2_rn(v10, v11);
                    *reinterpret_cast<__half2*>(&Vh[(plane + s    ) * 32 + d]) = p0;
                    *reinterpret_cast<__half2*>(&Vh[(plane + s + 8) * 32 + d]) = p1;
                    *reinterpret_cast<__half2*>(&Vh[CPYB_H + (plane + s + 1) * 32 + d]) = p0;
                    *reinterpret_cast<__half2*>(&Vh[CPYB_H + (plane + s + 9) * 32 + d]) = p1;
                } else if (MODE == 2) {
                    *reinterpret_cast<__half2*>(&g_offaw_h[(size_t)row0 * 288 + col]) =
                        __floats2half2_rn(v00, v01);
                    *reinterpret_cast<__half2*>(&g_offaw_h[(size_t)(row0 + 8) * 288 + col]) =
                        __floats2half2_rn(v10, v11);
                } else {
                    *reinterpret_cast<float2*>(&C[(size_t)row0 * N + col]) =
                        make_float2(v00, v01);
                    *reinterpret_cast<float2*>(&C[(size_t)(row0 + 8) * N + col]) =
                        make_float2(v10, v11);
                }
            }
        }
    }
}

// Merged value-proj (x<2) + offsets/aw-proj (x>=2) launch
__global__ void __launch_bounds__(256, 2) fused_proj_gemm(
    const __half* __restrict__ enc_h, const __half* __restrict__ valw,
    const float* __restrict__ valb,
    const __half* __restrict__ hid_h, const __half* __restrict__ obw,
    const float* __restrict__ obb)
{
    if (blockIdx.x < 2)
        hgemm_core<1>(enc_h, valw, valb, nullptr, 256, blockIdx.x * 128);
    else
        hgemm_core<2>(hid_h, obw, obb, nullptr, 288, (blockIdx.x - 2) * 128);
}

__global__ void __launch_bounds__(256, 2) out_proj_gemm(
    const __half* __restrict__ msda, const __half* __restrict__ outw,
    const float* __restrict__ outb, float* __restrict__ out)
{
    hgemm_core<0>(msda, outw, outb, out, 256, blockIdx.x * 128);
}

// ---------------------------------------------------------------------------
// Deformable sampling. Value fp16 [copy][B,H,Sp,D]; x-pixel pair = one
// aligned 128B load (copy picked by xb parity). Unit = 8 lanes: lanes 0-3
// pixel xb, 4-7 pixel xb+1; shfl_xor(4)-add.
// Params packed in ONE int4 (1 LDS.128/sample). Inner combine accumulates
// directly into fp16 (2 HFMA2 per j per sample); flush to fp32 per LEVEL
// (4-sample groups) -> ~13 issue slots/sample instead of ~27.
// ---------------------------------------------------------------------------
#define QB 8
#define NSAMP (QB * HEADS * LEVELS * POINTS)   // 768

__global__ void __launch_bounds__(256) msda_sample_kernel(
    const float* __restrict__ refp)
{
    __shared__ float s_aw[QB * HEADS * 12];
    __shared__ int4  s_pack[NSAMP];   // {off0, off1, wL(half2), wR(half2)}

    const int tid = threadIdx.x;
    const int bq0 = blockIdx.x * QB;

    // Phase 1a: softmax once per (q, h); fp16 logits at g_offaw_h[.., 192+]
    if (tid < QB * HEADS) {
        const int bqi = tid >> 3;
        const int h   = tid & 7;
        const __half* awp = g_offaw_h + (size_t)(bq0 + bqi) * 288 + 192 + h * 12;
        float w[12];
        float mx = -1e30f;
#pragma unroll
        for (int j = 0; j < 12; j++) { w[j] = __half2float(awp[j]); mx = fmaxf(mx, w[j]); }
        float s = 0.f;
#pragma unroll
        for (int j = 0; j < 12; j++) { w[j] = __expf(w[j] - mx); s += w[j]; }
        const float invs = 1.f / s;
#pragma unroll
        for (int j = 0; j < 12; j++) s_aw[tid * 12 + j] = w[j] * invs;
    }
    __syncthreads();

    // Phase 1b: per-sample params (3 samples per thread)
    const int lvlW[3]     = {128, 64, 32};
    const int lvlStart[3] = {0, 16384, 20480};
#pragma unroll
    for (int i = 0; i < 3; i++) {
        const int sid = tid + i * 256;
        const int bqi = sid / 96;
        const int r   = sid - bqi * 96;
        const int h   = r / 12;
        const int lp  = r - h * 12;
        const int l   = lp >> 2;

        const int bq = bq0 + bqi;
        const int b  = (bq >= NQUERY) ? 1 : 0;
        const int Wl = lvlW[l];
        const float fW = (float)Wl;

        const __half2 oxy = *reinterpret_cast<const __half2*>(
            g_offaw_h + (size_t)bq * 288 + h * 24 + lp * 2);
        const float ox = __low2float(oxy);
        const float oy = __high2float(oxy);
        const float rx = refp[(size_t)bq * 6 + l * 2 + 0];
        const float ry = refp[(size_t)bq * 6 + l * 2 + 1];

        const float x = fmaf(rx, fW, ox) - 0.5f;
        const float y = fmaf(ry, fW, oy) - 0.5f;
        const float xf = floorf(x), yf = floorf(y);
        const float wx = x - xf,    wy = y - yf;
        const int x0 = (int)xf, y0 = (int)yf;

        const int xb = min(max(x0, 0), Wl - 1);
        float wxl = (x0 >= 0 && x0 < Wl) ? (1.f - wx) : ((x0 == -1) ? wx : 0.f);
        float wxr = (x0 >= 0 && x0 + 1 < Wl) ? wx : 0.f;
        const int y0c = min(max(y0, 0), Wl - 1);
        const int y1c = min(max(y0 + 1, 0), Wl - 1);
        float wy0 = (y0 >= 0 && y0 < Wl) ? (1.f - wy) : 0.f;
        float wy1 = (y0 + 1 >= 0 && y0 + 1 < Wl) ? wy : 0.f;

        const float ws = s_aw[(bqi * 8 + h) * 12 + lp];
        // left side (rows 0,1), right side (rows 0,1)
        __half2 wL = __floats2half2_rn(ws * wy0 * wxl, ws * wy1 * wxl);
        __half2 wR = __floats2half2_rn(ws * wy0 * wxr, ws * wy1 * wxr);

        const int plane = (b * 8 + h) * SEQP;
        const int idx0  = lvlStart[l] + y0c * Wl + xb;
        const int idx1  = lvlStart[l] + y1c * Wl + xb;
        const int odd   = xb & 1;
        const int cbase = odd ? ((int)CPYB_U4 + 4) : 0;   // +1 pixel in copy B
        int4 pk;
        pk.x = cbase + (plane + idx0) * 4;
        pk.y = cbase + (plane + idx1) * 4;
        pk.z = *reinterpret_cast<int*>(&wL);
        pk.w = *reinterpret_cast<int*>(&wR);
        s_pack[sid] = pk;
    }
    __syncthreads();

    // Phase 2: gather. 2 passes x 32 units x 8 lanes.
    const uint4* __restrict__ VR = g_valrep;
    const int ll = tid & 7;
    const unsigned zero2 = 0u;
    const __half2 hzero = *reinterpret_cast<const __half2*>(&zero2);
#pragma unroll
    for (int pass = 0; pass < 2; pass++) {
        const int u   = (tid >> 3) + pass * 32;   // 0..63
        const int bqi = u >> 3;
        const int h   = u & 7;

        float acc[8];
#pragma unroll
        for (int c = 0; c < 8; c++) acc[c] = 0.f;

#pragma unroll
        for (int l = 0; l < LEVELS; l++) {
            __half2 hacc[4] = { hzero, hzero, hzero, hzero };
#pragma unroll
            for (int p = 0; p < POINTS; p++) {
                const int sid = u * 12 + l * 4 + p;
                const int4 pk = s_pack[sid];      // single LDS.128 broadcast
                uint4 r0 = VR[pk.x + ll];
                uint4 r1 = VR[pk.y + ll];
                const int wsel = (ll & 4) ? pk.w : pk.z;
                const __half2 wpair = *reinterpret_cast<const __half2*>(&wsel);
                const __half2 wa2 = __half2half2(__low2half(wpair));   // row0
                const __half2 wb2 = __half2half2(__high2half(wpair));  // row1
                const __half2* p0 = reinterpret_cast<const __half2*>(&r0);
                const __half2* p1 = reinterpret_cast<const __half2*>(&r1);
#pragma unroll
                for (int j = 0; j < 4; j++) {
                    hacc[j] = __hfma2(p0[j], wa2, hacc[j]);
                    hacc[j] = __hfma2(p1[j], wb2, hacc[j]);
                }
            }
            // flush level group to fp32 master
#pragma unroll
            for (int j = 0; j < 4; j++) {
                float2 ft = __half22float2(hacc[j]);
                acc[2*j]   += ft.x;
                acc[2*j+1] += ft.y;
            }
        }
#pragma unroll
        for (int c = 0; c < 8; c++)
            acc[c] += __shfl_xor_sync(0xffffffffu, acc[c], 4);

        if (ll < 4) {
            __half2 o0 = __floats2half2_rn(acc[0], acc[1]);
            __half2 o1 = __floats2half2_rn(acc[2], acc[3]);
            __half2 o2 = __floats2half2_rn(acc[4], acc[5]);
            __half2 o3 = __floats2half2_rn(acc[6], acc[7]);
            uint4 ov;
            ov.x = *reinterpret_cast<unsigned*>(&o0);
            ov.y = *reinterpret_cast<unsigned*>(&o1);
            ov.z = *reinterpret_cast<unsigned*>(&o2);
            ov.w = *reinterpret_cast<unsigned*>(&o3);
            uint4* outp = reinterpret_cast<uint4*>(g_msda_h)
                        + (size_t)(bq0 + bqi) * 32 + h * 4 + ll;
            *outp = ov;
        }
    }
}

// ---------------------------------------------------------------------------

extern "C" void kernel_launch(void* const* d_in, const int* in_sizes, int n_in,
                              void* d_out, int out_size)
{
    const float* hidden = (const float*)d_in[0];   // [B,Q,256]
    const float* enc    = (const float*)d_in[1];   // [B,S,256]
    const float* refp   = (const float*)d_in[2];   // [B,Q,L,2]
    // d_in[3] = spatial_shapes (static, hardcoded)
    const float* off_w  = (const float*)d_in[4];   // [192,256]
    const float* off_b  = (const float*)d_in[5];
    const float* aw_w   = (const float*)d_in[6];   // [96,256]
    const float* aw_b   = (const float*)d_in[7];
    const float* val_w  = (const float*)d_in[8];   // [256,256]
    const float* val_b  = (const float*)d_in[9];
    const float* out_w  = (const float*)d_in[10];  // [256,256]
    const float* out_b  = (const float*)d_in[11];
    float* out = (float*)d_out;

    __half *p_hid_h, *p_enc_h, *p_msda_h, *p_valw, *p_outw, *p_obw;
    float  *p_obb;
    cudaGetSymbolAddress((void**)&p_hid_h,  g_hidden_h);
    cudaGetSymbolAddress((void**)&p_enc_h,  g_enc_h);
    cudaGetSymbolAddress((void**)&p_msda_h, g_msda_h);
    cudaGetSymbolAddress((void**)&p_valw,   g_valw_h);
    cudaGetSymbolAddress((void**)&p_outw,   g_outw_h);
    cudaGetSymbolAddress((void**)&p_obw,    g_obw_h);
    cudaGetSymbolAddress((void**)&p_obb,    g_obb);

    static int smem_set = 0;
    const int SMEM_BYTES = 65536;
    if (!smem_set) {
        cudaFuncSetAttribute(fused_proj_gemm,
                             cudaFuncAttributeMaxDynamicSharedMemorySize, SMEM_BYTES);
        cudaFuncSetAttribute(out_proj_gemm,
                             cudaFuncAttributeMaxDynamicSharedMemorySize, SMEM_BYTES);
        smem_set = 1;
    }

    const int MB = MROWS / 128;   // 336
    dim3 blk(256);

    // all fp32 -> fp16 conversions + bias concat in one launch
    f2h_mega<<<(SEG_AWW + 255) / 256, blk>>>(
        (const float4*)hidden, (const float4*)enc,
        (const float4*)val_w, (const float4*)out_w,
        (const float4*)off_w, (const float4*)aw_w,
        off_b, aw_b);

    // merged: value projection (x<2) + fused off/aw projection (x>=2)
    fused_proj_gemm<<<dim3(5, MB), blk, SMEM_BYTES>>>(p_enc_h, p_valw, val_b,
                                                      p_hid_h, p_obw, p_obb);

    // deformable sampling -> fp16 msda
    msda_sample_kernel<<<MROWS / QB, blk>>>(refp);

    // output projection (fp32 out to d_out)
    out_proj_gemm<<<dim3(2, MB), blk, SMEM_BYTES>>>(p_msda_h, p_outw, out_b, out);
}